// round 15
// baseline (speedup 1.0000x reference)
#include <cuda_runtime.h>
#include <cuda_fp16.h>
#include <math.h>

#define Nn 100000
#define Ee 1600000
#define Hh 64
#define NHEADS 4
#define CC 256           // NHEADS * Hh
#define EPSN 1e-5f
#define NSB 98           // scan blocks: 98*1024 >= Nn

// ---------------- scratch (device bss, no allocation) ----------------
__device__ __align__(16) float d_nacc[Nn * 8];        // deg, agg[5], easum[2]
__device__ __align__(16) float d_h[Nn * Hh];
__device__ __align__(16) float d_la[Nn * 2];
__device__ int d_ideg[Nn];
__device__ float d_sum1[2 * Hh];
__device__ __align__(16) float d_wT[Hh * CC];          // transposed gat_w: [k][t]
__device__ float d_weff[NHEADS * 2];
__device__ __align__(16) __half d_xph[(size_t)Nn * CC];   // xp in fp16
__device__ __align__(16) float d_asrc[Nn * NHEADS];
__device__ __align__(16) float d_adst[Nn * NHEADS];
__device__ int d_ptr[Nn];                              // CSR start
__device__ int d_cur[Nn];                              // CSR cursor -> end
__device__ int d_bsum[NSB];
__device__ int d_boff[NSB];
__device__ __align__(16) uint4 d_erec[Ee];             // 16B: {half2 e01, half2 e23, src, pad}
__device__ __align__(16) __half d_gh[(size_t)Nn * CC]; // g in fp16
__device__ float d_sum2[2 * CC];

// ---------------- helpers ----------------
__device__ __forceinline__ void red_add_v4(float* addr, float a, float b, float c, float d) {
    asm volatile("red.global.add.v4.f32 [%0], {%1,%2,%3,%4};"
                 :: "l"(addr), "f"(a), "f"(b), "f"(c), "f"(d) : "memory");
}
__device__ __forceinline__ float lrelu(float a) { return a > 0.f ? a : 0.2f * a; }
__device__ __forceinline__ float eluf(float a)  { return a > 0.f ? a : expm1f(a); }

// ---------------- k_prep: transpose gat_w + weff + zero sums ----------------
__global__ void k_prep(const float* __restrict__ gat_w,
                       const float* __restrict__ att_e,
                       const float* __restrict__ gat_we) {
    int t = threadIdx.x;  // 256
    for (int k = 0; k < Hh; ++k)
        d_wT[k * CC + t] = gat_w[t * Hh + k];
    if (t < NHEADS * 2) {
        int h = t >> 1, kk = t & 1;
        float s = 0.f;
        for (int c = 0; c < Hh; ++c)
            s += gat_we[(h * Hh + c) * 2 + kk] * att_e[h * Hh + c];
        d_weff[t] = s;
    }
    if (t < 2 * Hh) d_sum1[t] = 0.f;
    d_sum2[t] = 0.f;
    d_sum2[CC + t] = 0.f;
}

// ---------------- k_eagg: per-edge deg/agg/easum ----------------
__global__ void k_eagg(const int* __restrict__ src, const int* __restrict__ dst,
                       const float* __restrict__ x, const float* __restrict__ ea) {
    int e = blockIdx.x * blockDim.x + threadIdx.x;
    if (e >= Ee) return;
    int s = src[e], d = dst[e];
    const float* xs = x + s * 5;
    float x0 = xs[0], x1 = xs[1], x2 = xs[2], x3 = xs[3], x4 = xs[4];
    float2 e2 = ((const float2*)ea)[e];
    float* na = d_nacc + d * 8;
    red_add_v4(na,     1.f, x0, x1, x2);
    red_add_v4(na + 4, x3, x4, e2.x, e2.y);
}

// ---------------- k_node1: SAGE + norm1 stats + compact deg ----------------
__global__ void k_node1(const float* __restrict__ x,
                        const float* __restrict__ wl,
                        const float* __restrict__ bl,
                        const float* __restrict__ wr) {
    __shared__ float sWl[Hh * 5], sWr[Hh * 5], sBl[Hh], ssum[Hh], ssum2[Hh];
    int tid = threadIdx.x;  // 256
    for (int i = tid; i < Hh * 5; i += 256) { sWl[i] = wl[i]; sWr[i] = wr[i]; }
    if (tid < Hh) { sBl[tid] = bl[tid]; ssum[tid] = 0.f; ssum2[tid] = 0.f; }
    __syncthreads();
    int nl = tid >> 6, c = tid & 63;
    int n = blockIdx.x * 4 + nl;
    float hv = 0.f;
    if (n < Nn) {
        const float* na = d_nacc + n * 8;
        float degr = na[0];
        float deg = fmaxf(degr, 1.f);
        float inv = 1.f / deg;
        float a0 = na[1] * inv, a1 = na[2] * inv, a2 = na[3] * inv,
              a3 = na[4] * inv, a4 = na[5] * inv;
        const float* xr = x + n * 5;
        const float* wlr = sWl + c * 5;
        const float* wrr = sWr + c * 5;
        hv = sBl[c]
           + wlr[0]*a0 + wlr[1]*a1 + wlr[2]*a2 + wlr[3]*a3 + wlr[4]*a4
           + wrr[0]*xr[0] + wrr[1]*xr[1] + wrr[2]*xr[2] + wrr[3]*xr[3] + wrr[4]*xr[4];
        d_h[n * Hh + c] = hv;
        if (c < 2) d_la[n * 2 + c] = na[6 + c] * inv;
        if (c == 0) d_ideg[n] = (int)degr;
    }
    atomicAdd(&ssum[c], hv);
    atomicAdd(&ssum2[c], hv * hv);
    __syncthreads();
    if (tid < Hh) {
        atomicAdd(&d_sum1[tid], ssum[tid]);
        atomicAdd(&d_sum1[Hh + tid], ssum2[tid]);
    }
}

// ---------------- k_scan1: per-block exclusive scan (coalesced) ----------------
__global__ void k_scan1() {
    __shared__ int sh[1024];
    const int t = threadIdx.x;
    const int n = blockIdx.x * 1024 + t;
    int v = (n < Nn) ? d_ideg[n] : 0;
    sh[t] = v;
    __syncthreads();
    for (int d = 1; d < 1024; d <<= 1) {
        int u = (t >= d) ? sh[t - d] : 0;
        __syncthreads();
        sh[t] += u;
        __syncthreads();
    }
    if (n < Nn) d_ptr[n] = sh[t] - v;   // block-local exclusive prefix
    if (t == 1023) d_bsum[blockIdx.x] = sh[1023];
}

// ---------------- k_scan2: scan the 98 block sums ----------------
__global__ void k_scan2() {
    __shared__ int sh[128];
    const int t = threadIdx.x;  // 128
    int v = (t < NSB) ? d_bsum[t] : 0;
    sh[t] = v;
    __syncthreads();
    for (int d = 1; d < 128; d <<= 1) {
        int u = (t >= d) ? sh[t - d] : 0;
        __syncthreads();
        sh[t] += u;
        __syncthreads();
    }
    if (t < NSB) d_boff[t] = sh[t] - v;
}

// ---------------- k_xp: scan3-fold + inline stats1 + norm1+ELU + GEMM (16 nodes/block) ----------------
__global__ void k_xp(const float* __restrict__ n1b,
                     const float* __restrict__ n1w,
                     const float* __restrict__ n1ms,
                     const float* __restrict__ att_s,
                     const float* __restrict__ att_d) {
    __shared__ unsigned long long h1d[16 * Hh];   // (hk,hk) packed pairs
    const int q = threadIdx.x;  // 64
    const int nb = blockIdx.x * 16;
    // fold of scan3: finalize CSR offsets for this block's 16 nodes
    if (q < 16) {
        int n2 = nb + q;
        if (n2 < Nn) {
            int p = d_ptr[n2] + d_boff[n2 >> 10];
            d_ptr[n2] = p;
            d_cur[n2] = p;
        }
    }
    // inline GraphNorm stats (d_sum1 finalized by k_node1)
    float m  = d_sum1[q]      * (1.f / Nn);
    float m2 = d_sum1[Hh + q] * (1.f / Nn);
    float msv = n1ms[q];
    float var = m2 - (2.f * msv - msv * msv) * m * m;
    const float mu = msv * m;
    const float sc = n1w[q] * rsqrtf(var + EPSN);
    const float bb = n1b[q];
    #pragma unroll
    for (int i = 0; i < 16; ++i) {
        int n = nb + i;
        float v = 0.f;
        if (n < Nn) {
            float y = sc * (d_h[n * Hh + q] - mu) + bb;
            v = eluf(y);
        }
        unsigned long long pk;
        asm("mov.b64 %0, {%1, %2};" : "=l"(pk) : "f"(v), "f"(v));
        h1d[i * Hh + q] = pk;
    }
    __syncthreads();
    unsigned long long accA[16], accB[16];
    #pragma unroll
    for (int i = 0; i < 16; ++i) { accA[i] = 0ull; accB[i] = 0ull; }
    const ulonglong2* wt = (const ulonglong2*)d_wT;
    #pragma unroll 2
    for (int k = 0; k < Hh; ++k) {
        ulonglong2 w2 = wt[k * 64 + q];
        #pragma unroll
        for (int i = 0; i < 16; ++i) {
            unsigned long long h2 = h1d[i * Hh + k];
            asm("fma.rn.f32x2 %0, %1, %2, %0;" : "+l"(accA[i]) : "l"(w2.x), "l"(h2));
            asm("fma.rn.f32x2 %0, %1, %2, %0;" : "+l"(accB[i]) : "l"(w2.y), "l"(h2));
        }
    }
    const int head = q >> 4;
    const int cb = (q & 15) * 4;
    float as0 = att_s[head * Hh + cb],     as1 = att_s[head * Hh + cb + 1],
          as2 = att_s[head * Hh + cb + 2], as3 = att_s[head * Hh + cb + 3];
    float ad0 = att_d[head * Hh + cb],     ad1 = att_d[head * Hh + cb + 1],
          ad2 = att_d[head * Hh + cb + 2], ad3 = att_d[head * Hh + cb + 3];
    #pragma unroll
    for (int i = 0; i < 16; ++i) {
        int n = nb + i;
        float o0, o1, o2, o3;
        asm("mov.b64 {%0, %1}, %2;" : "=f"(o0), "=f"(o1) : "l"(accA[i]));
        asm("mov.b64 {%0, %1}, %2;" : "=f"(o2), "=f"(o3) : "l"(accB[i]));
        float ps = o0 * as0 + o1 * as1 + o2 * as2 + o3 * as3;
        float pd = o0 * ad0 + o1 * ad1 + o2 * ad2 + o3 * ad3;
        #pragma unroll
        for (int off = 8; off > 0; off >>= 1) {
            ps += __shfl_xor_sync(0xffffffffu, ps, off);
            pd += __shfl_xor_sync(0xffffffffu, pd, off);
        }
        if (n < Nn) {
            __half2 ha = __floats2half2_rn(o0, o1);
            __half2 hb = __floats2half2_rn(o2, o3);
            uint2 st;
            st.x = *(unsigned int*)&ha;
            st.y = *(unsigned int*)&hb;
            ((uint2*)d_xph)[(size_t)n * 64 + q] = st;
            if ((q & 15) == 0) {
                d_asrc[n * NHEADS + head] = ps;
                d_adst[n * NHEADS + head] = pd;
            }
        }
    }
}

// ---------------- k_fill: scatter edges into CSR with final attention weight (fp16) ----------------
__global__ void k_fill(const int* __restrict__ src, const int* __restrict__ dst,
                       const float* __restrict__ ea) {
    int e = blockIdx.x * blockDim.x + threadIdx.x;
    if (e >= Ee) return;
    int s = src[e], d = dst[e];
    float4 as = ((const float4*)d_asrc)[s];
    float4 ad = ((const float4*)d_adst)[d];
    float2 e2 = ((const float2*)ea)[e];
    float ex0 = __expf(lrelu(as.x + ad.x + e2.x * d_weff[0] + e2.y * d_weff[1]));
    float ex1 = __expf(lrelu(as.y + ad.y + e2.x * d_weff[2] + e2.y * d_weff[3]));
    float ex2 = __expf(lrelu(as.z + ad.z + e2.x * d_weff[4] + e2.y * d_weff[5]));
    float ex3 = __expf(lrelu(as.w + ad.w + e2.x * d_weff[6] + e2.y * d_weff[7]));
    int pos = atomicAdd(&d_cur[d], 1);
    __half2 e01 = __floats2half2_rn(ex0, ex1);
    __half2 e23 = __floats2half2_rn(ex2, ex3);
    uint4 r;
    r.x = *(unsigned int*)&e01;
    r.y = *(unsigned int*)&e23;
    r.z = (unsigned int)s;
    r.w = 0u;
    d_erec[pos] = r;
}

// ---------------- k_gat: warp-per-node, 4-deep pipelined 512B gathers ----------------
__global__ void __launch_bounds__(256, 4) k_gat(const float* __restrict__ gat_b) {
    __shared__ float sred[8][CC];   // 8KB
    const int t = threadIdx.x;      // 256 = 8 warps
    const int w = t >> 5, lane = t & 31;
    const int head = lane >> 3;
    const int n = blockIdx.x * 8 + w;
    float sacc[8], s2acc[8];
    #pragma unroll
    for (int j = 0; j < 8; ++j) { sacc[j] = 0.f; s2acc[j] = 0.f; }

    if (n < Nn) {
        const float4 b0 = *(const float4*)(gat_b + lane * 8);
        const float4 b1 = *(const float4*)(gat_b + lane * 8 + 4);
        const float we0 = d_weff[head * 2], we1 = d_weff[head * 2 + 1];
        const float ad = d_adst[n * NHEADS + head];
        const float as = d_asrc[n * NHEADS + head];
        const float la0 = d_la[n * 2], la1 = d_la[n * 2 + 1];
        float es = __expf(lrelu(as + ad + la0 * we0 + la1 * we1));
        float den = es;
        float acc[8];
        {
            uint4 xv = *(const uint4*)(d_xph + (size_t)n * CC + lane * 8);
            float2 f0 = __half22float2(*(__half2*)&xv.x);
            float2 f1 = __half22float2(*(__half2*)&xv.y);
            float2 f2 = __half22float2(*(__half2*)&xv.z);
            float2 f3 = __half22float2(*(__half2*)&xv.w);
            acc[0] = es * f0.x; acc[1] = es * f0.y;
            acc[2] = es * f1.x; acc[3] = es * f1.y;
            acc[4] = es * f2.x; acc[5] = es * f2.y;
            acc[6] = es * f3.x; acc[7] = es * f3.y;
        }
        const int p0 = d_ptr[n], p1 = d_cur[n];
        uint4 cc[4];
        #pragma unroll
        for (int j = 0; j < 4; ++j)
            cc[j] = (p0 + j < p1) ? d_erec[p0 + j] : make_uint4(0u, 0u, 0u, 0u);
        for (int i = p0; i < p1; i += 4) {
            float ex[4]; int ss[4];
            #pragma unroll
            for (int j = 0; j < 4; ++j) {
                unsigned int pair = (head < 2) ? cc[j].x : cc[j].y;
                __half2 h2 = *(__half2*)&pair;
                ex[j] = (head & 1) ? __high2float(h2) : __low2float(h2);
                ss[j] = (int)cc[j].z;
            }
            uint4 xv[4];
            #pragma unroll
            for (int j = 0; j < 4; ++j)
                xv[j] = *(const uint4*)(d_xph + (size_t)ss[j] * CC + lane * 8);
            #pragma unroll
            for (int j = 0; j < 4; ++j)
                cc[j] = (i + 4 + j < p1) ? d_erec[i + 4 + j] : make_uint4(0u, 0u, 0u, 0u);
            #pragma unroll
            for (int j = 0; j < 4; ++j) {
                den += ex[j];
                float2 f0 = __half22float2(*(__half2*)&xv[j].x);
                float2 f1 = __half22float2(*(__half2*)&xv[j].y);
                float2 f2 = __half22float2(*(__half2*)&xv[j].z);
                float2 f3 = __half22float2(*(__half2*)&xv[j].w);
                acc[0] = fmaf(ex[j], f0.x, acc[0]); acc[1] = fmaf(ex[j], f0.y, acc[1]);
                acc[2] = fmaf(ex[j], f1.x, acc[2]); acc[3] = fmaf(ex[j], f1.y, acc[3]);
                acc[4] = fmaf(ex[j], f2.x, acc[4]); acc[5] = fmaf(ex[j], f2.y, acc[5]);
                acc[6] = fmaf(ex[j], f3.x, acc[6]); acc[7] = fmaf(ex[j], f3.y, acc[7]);
            }
        }
        float inv = 1.f / den;
        float g0 = acc[0] * inv + b0.x, g1 = acc[1] * inv + b0.y;
        float g2 = acc[2] * inv + b0.z, g3 = acc[3] * inv + b0.w;
        float g4 = acc[4] * inv + b1.x, g5 = acc[5] * inv + b1.y;
        float g6 = acc[6] * inv + b1.z, g7 = acc[7] * inv + b1.w;
        __half2 h01 = __floats2half2_rn(g0, g1);
        __half2 h23 = __floats2half2_rn(g2, g3);
        __half2 h45 = __floats2half2_rn(g4, g5);
        __half2 h67 = __floats2half2_rn(g6, g7);
        uint4 stv;
        stv.x = *(unsigned int*)&h01;
        stv.y = *(unsigned int*)&h23;
        stv.z = *(unsigned int*)&h45;
        stv.w = *(unsigned int*)&h67;
        __stcs((uint4*)(d_gh + (size_t)n * CC + lane * 8), stv);
        sacc[0] = g0; s2acc[0] = g0 * g0;
        sacc[1] = g1; s2acc[1] = g1 * g1;
        sacc[2] = g2; s2acc[2] = g2 * g2;
        sacc[3] = g3; s2acc[3] = g3 * g3;
        sacc[4] = g4; s2acc[4] = g4 * g4;
        sacc[5] = g5; s2acc[5] = g5 * g5;
        sacc[6] = g6; s2acc[6] = g6 * g6;
        sacc[7] = g7; s2acc[7] = g7 * g7;
    }
    #pragma unroll
    for (int j = 0; j < 8; ++j) sred[w][lane * 8 + j] = sacc[j];
    __syncthreads();
    float ts = 0.f;
    #pragma unroll
    for (int ww = 0; ww < 8; ++ww) ts += sred[ww][t];
    __syncthreads();
    #pragma unroll
    for (int j = 0; j < 8; ++j) sred[w][lane * 8 + j] = s2acc[j];
    __syncthreads();
    float ts2 = 0.f;
    #pragma unroll
    for (int ww = 0; ww < 8; ++ww) ts2 += sred[ww][t];
    atomicAdd(&d_sum2[t], ts);
    atomicAdd(&d_sum2[CC + t], ts2);
}

// ---------------- k_out: inline stats2 + 8 nodes per block ----------------
__global__ void k_out(const float* __restrict__ n2b,
                      const float* __restrict__ n2w,
                      const float* __restrict__ n2ms,
                      const float* __restrict__ ow,
                      const float* __restrict__ ob,
                      float* __restrict__ out) {
    __shared__ float red[8][8][4];   // [warp][node][out]
    const int nb = blockIdx.x * 8;
    const int t = threadIdx.x;  // 256
    const int w = t >> 5;
    const float w0 = ow[t], w1 = ow[CC + t], w2 = ow[2 * CC + t], w3 = ow[3 * CC + t];
    // inline stats2 (d_sum2 finalized by k_gat)
    float m  = d_sum2[t]      * (1.f / Nn);
    float m2 = d_sum2[CC + t] * (1.f / Nn);
    float msv = n2ms[t];
    float var = m2 - (2.f * msv - msv * msv) * m * m;
    const float mu = msv * m;
    const float sc = n2w[t] * rsqrtf(var + EPSN);
    const float bb = n2b[t];
    #pragma unroll
    for (int i = 0; i < 8; ++i) {
        int n = nb + i;
        float y = 0.f;
        if (n < Nn) {
            float gv = __half2float(__ldcs(d_gh + (size_t)n * CC + t));
            y = eluf(sc * (gv - mu) + bb);
        }
        float p0 = y * w0, p1 = y * w1, p2 = y * w2, p3 = y * w3;
        #pragma unroll
        for (int off = 16; off > 0; off >>= 1) {
            p0 += __shfl_xor_sync(0xffffffffu, p0, off);
            p1 += __shfl_xor_sync(0xffffffffu, p1, off);
            p2 += __shfl_xor_sync(0xffffffffu, p2, off);
            p3 += __shfl_xor_sync(0xffffffffu, p3, off);
        }
        if ((t & 31) == 0) {
            red[w][i][0] = p0; red[w][i][1] = p1;
            red[w][i][2] = p2; red[w][i][3] = p3;
        }
    }
    __syncthreads();
    if (t < 32) {
        int i = t >> 2, o = t & 3;
        int n = nb + i;
        if (n < Nn) {
            float s = ob[o];
            #pragma unroll
            for (int ww = 0; ww < 8; ++ww) s += red[ww][i][o];
            out[n * 4 + o] = fmaxf(s, 0.f);
        }
    }
}

// ---------------- host ----------------
extern "C" void kernel_launch(void* const* d_in, const int* in_sizes, int n_in,
                              void* d_out, int out_size) {
    const float* x     = (const float*)d_in[0];
    const float* ea    = (const float*)d_in[1];
    const float* swl   = (const float*)d_in[2];
    const float* sbl   = (const float*)d_in[3];
    const float* swr   = (const float*)d_in[4];
    const float* n1w   = (const float*)d_in[5];
    const float* n1b   = (const float*)d_in[6];
    const float* n1ms  = (const float*)d_in[7];
    const float* gatw  = (const float*)d_in[8];
    const float* atts  = (const float*)d_in[9];
    const float* attd  = (const float*)d_in[10];
    const float* atte  = (const float*)d_in[11];
    const float* gatwe = (const float*)d_in[12];
    const float* gatb  = (const float*)d_in[13];
    const float* n2w   = (const float*)d_in[14];
    const float* n2b   = (const float*)d_in[15];
    const float* n2ms  = (const float*)d_in[16];
    const float* outw  = (const float*)d_in[17];
    const float* outb  = (const float*)d_in[18];
    const int*   eidx  = (const int*)d_in[19];
    const int* src = eidx;
    const int* dst = eidx + Ee;
    float* out = (float*)d_out;

    void* p_nacc;
    cudaGetSymbolAddress(&p_nacc, d_nacc);
    cudaMemsetAsync(p_nacc, 0, sizeof(float) * Nn * 8);

    k_prep<<<1, 256>>>(gatw, atte, gatwe);
    k_eagg<<<(Ee + 255) / 256, 256>>>(src, dst, x, ea);
    k_node1<<<(Nn + 3) / 4, 256>>>(x, swl, sbl, swr);
    k_scan1<<<NSB, 1024>>>();
    k_scan2<<<1, 128>>>();
    k_xp<<<(Nn + 15) / 16, 64>>>(n1b, n1w, n1ms, atts, attd);
    k_fill<<<(Ee + 255) / 256, 256>>>(src, dst, ea);
    k_gat<<<(Nn + 7) / 8, 256>>>(gatb);
    k_out<<<(Nn + 7) / 8, 256>>>(n2b, n2w, n2ms, outw, outb, out);
}

// round 16
// speedup vs baseline: 1.0268x; 1.0268x over previous
#include <cuda_runtime.h>
#include <cuda_fp16.h>
#include <math.h>

#define Nn 100000
#define Ee 1600000
#define Hh 64
#define NHEADS 4
#define CC 256           // NHEADS * Hh
#define EPSN 1e-5f
#define NSB 98           // scan blocks: 98*1024 >= Nn

// ---------------- scratch (device bss, no allocation) ----------------
__device__ __align__(16) float d_nacc[Nn * 8];        // deg, agg[5], easum[2]
__device__ __align__(16) float d_h[Nn * Hh];
__device__ __align__(16) float d_la[Nn * 2];
__device__ int d_ideg[Nn];
__device__ float d_sum1[2 * Hh];
__device__ __align__(16) float d_wT[Hh * CC];          // transposed gat_w: [k][t]
__device__ float d_weff[NHEADS * 2];
__device__ __align__(16) __half d_xph[(size_t)Nn * CC];   // xp in fp16
__device__ __align__(16) float d_asrc[Nn * NHEADS];
__device__ __align__(16) float d_adst[Nn * NHEADS];
__device__ int d_ptr[Nn];                              // CSR start
__device__ int d_cur[Nn];                              // CSR cursor -> end
__device__ int d_bsum[NSB];
__device__ int d_boff[NSB];
__device__ __align__(16) uint4 d_erec[Ee];             // 16B: {half2 e01, half2 e23, src, pad}
__device__ __align__(16) __half d_gh[(size_t)Nn * CC]; // g in fp16
__device__ float d_sum2[2 * CC];

// ---------------- helpers ----------------
__device__ __forceinline__ void red_add_v4(float* addr, float a, float b, float c, float d) {
    asm volatile("red.global.add.v4.f32 [%0], {%1,%2,%3,%4};"
                 :: "l"(addr), "f"(a), "f"(b), "f"(c), "f"(d) : "memory");
}
__device__ __forceinline__ float lrelu(float a) { return a > 0.f ? a : 0.2f * a; }
__device__ __forceinline__ float eluf(float a)  { return a > 0.f ? a : expm1f(a); }

// ---------------- k_prep: transpose gat_w + weff + zero sums ----------------
__global__ void k_prep(const float* __restrict__ gat_w,
                       const float* __restrict__ att_e,
                       const float* __restrict__ gat_we) {
    int t = threadIdx.x;  // 256
    for (int k = 0; k < Hh; ++k)
        d_wT[k * CC + t] = gat_w[t * Hh + k];
    if (t < NHEADS * 2) {
        int h = t >> 1, kk = t & 1;
        float s = 0.f;
        for (int c = 0; c < Hh; ++c)
            s += gat_we[(h * Hh + c) * 2 + kk] * att_e[h * Hh + c];
        d_weff[t] = s;
    }
    if (t < 2 * Hh) d_sum1[t] = 0.f;
    d_sum2[t] = 0.f;
    d_sum2[CC + t] = 0.f;
}

// ---------------- k_eagg: per-edge deg/agg/easum ----------------
__global__ void k_eagg(const int* __restrict__ src, const int* __restrict__ dst,
                       const float* __restrict__ x, const float* __restrict__ ea) {
    int e = blockIdx.x * blockDim.x + threadIdx.x;
    if (e >= Ee) return;
    int s = src[e], d = dst[e];
    const float* xs = x + s * 5;
    float x0 = xs[0], x1 = xs[1], x2 = xs[2], x3 = xs[3], x4 = xs[4];
    float2 e2 = ((const float2*)ea)[e];
    float* na = d_nacc + d * 8;
    red_add_v4(na,     1.f, x0, x1, x2);
    red_add_v4(na + 4, x3, x4, e2.x, e2.y);
}

// ---------------- k_node1: SAGE + norm1 stats + compact deg ----------------
__global__ void k_node1(const float* __restrict__ x,
                        const float* __restrict__ wl,
                        const float* __restrict__ bl,
                        const float* __restrict__ wr) {
    __shared__ float sWl[Hh * 5], sWr[Hh * 5], sBl[Hh], ssum[Hh], ssum2[Hh];
    int tid = threadIdx.x;  // 256
    for (int i = tid; i < Hh * 5; i += 256) { sWl[i] = wl[i]; sWr[i] = wr[i]; }
    if (tid < Hh) { sBl[tid] = bl[tid]; ssum[tid] = 0.f; ssum2[tid] = 0.f; }
    __syncthreads();
    int nl = tid >> 6, c = tid & 63;
    int n = blockIdx.x * 4 + nl;
    float hv = 0.f;
    if (n < Nn) {
        const float* na = d_nacc + n * 8;
        float degr = na[0];
        float deg = fmaxf(degr, 1.f);
        float inv = 1.f / deg;
        float a0 = na[1] * inv, a1 = na[2] * inv, a2 = na[3] * inv,
              a3 = na[4] * inv, a4 = na[5] * inv;
        const float* xr = x + n * 5;
        const float* wlr = sWl + c * 5;
        const float* wrr = sWr + c * 5;
        hv = sBl[c]
           + wlr[0]*a0 + wlr[1]*a1 + wlr[2]*a2 + wlr[3]*a3 + wlr[4]*a4
           + wrr[0]*xr[0] + wrr[1]*xr[1] + wrr[2]*xr[2] + wrr[3]*xr[3] + wrr[4]*xr[4];
        d_h[n * Hh + c] = hv;
        if (c < 2) d_la[n * 2 + c] = na[6 + c] * inv;
        if (c == 0) d_ideg[n] = (int)degr;
    }
    atomicAdd(&ssum[c], hv);
    atomicAdd(&ssum2[c], hv * hv);
    __syncthreads();
    if (tid < Hh) {
        atomicAdd(&d_sum1[tid], ssum[tid]);
        atomicAdd(&d_sum1[Hh + tid], ssum2[tid]);
    }
}

// ---------------- k_scan1: per-block exclusive scan (coalesced) ----------------
__global__ void k_scan1() {
    __shared__ int sh[1024];
    const int t = threadIdx.x;
    const int n = blockIdx.x * 1024 + t;
    int v = (n < Nn) ? d_ideg[n] : 0;
    sh[t] = v;
    __syncthreads();
    for (int d = 1; d < 1024; d <<= 1) {
        int u = (t >= d) ? sh[t - d] : 0;
        __syncthreads();
        sh[t] += u;
        __syncthreads();
    }
    if (n < Nn) d_ptr[n] = sh[t] - v;   // block-local exclusive prefix
    if (t == 1023) d_bsum[blockIdx.x] = sh[1023];
}

// ---------------- k_scan2: scan the 98 block sums ----------------
__global__ void k_scan2() {
    __shared__ int sh[128];
    const int t = threadIdx.x;  // 128
    int v = (t < NSB) ? d_bsum[t] : 0;
    sh[t] = v;
    __syncthreads();
    for (int d = 1; d < 128; d <<= 1) {
        int u = (t >= d) ? sh[t - d] : 0;
        __syncthreads();
        sh[t] += u;
        __syncthreads();
    }
    if (t < NSB) d_boff[t] = sh[t] - v;
}

// ---------------- k_xp: scan3-fold + inline stats1 + norm1+ELU + GEMM (8 nodes/block) ----------------
__global__ void k_xp(const float* __restrict__ n1b,
                     const float* __restrict__ n1w,
                     const float* __restrict__ n1ms,
                     const float* __restrict__ att_s,
                     const float* __restrict__ att_d) {
    __shared__ unsigned long long h1d[8 * Hh];   // (hk,hk) packed pairs
    const int q = threadIdx.x;  // 64
    const int nb = blockIdx.x * 8;
    // fold of scan3: finalize CSR offsets for this block's 8 nodes
    if (q < 8) {
        int n2 = nb + q;
        if (n2 < Nn) {
            int p = d_ptr[n2] + d_boff[n2 >> 10];
            d_ptr[n2] = p;
            d_cur[n2] = p;
        }
    }
    // inline GraphNorm stats (d_sum1 finalized by k_node1)
    float m  = d_sum1[q]      * (1.f / Nn);
    float m2 = d_sum1[Hh + q] * (1.f / Nn);
    float msv = n1ms[q];
    float var = m2 - (2.f * msv - msv * msv) * m * m;
    const float mu = msv * m;
    const float sc = n1w[q] * rsqrtf(var + EPSN);
    const float bb = n1b[q];
    #pragma unroll
    for (int i = 0; i < 8; ++i) {
        int n = nb + i;
        float v = 0.f;
        if (n < Nn) {
            float y = sc * (d_h[n * Hh + q] - mu) + bb;
            v = eluf(y);
        }
        unsigned long long pk;
        asm("mov.b64 %0, {%1, %2};" : "=l"(pk) : "f"(v), "f"(v));
        h1d[i * Hh + q] = pk;
    }
    __syncthreads();
    unsigned long long accA[8], accB[8];
    #pragma unroll
    for (int i = 0; i < 8; ++i) { accA[i] = 0ull; accB[i] = 0ull; }
    const ulonglong2* wt = (const ulonglong2*)d_wT;
    #pragma unroll 4
    for (int k = 0; k < Hh; ++k) {
        ulonglong2 w2 = wt[k * 64 + q];
        #pragma unroll
        for (int i = 0; i < 8; ++i) {
            unsigned long long h2 = h1d[i * Hh + k];
            asm("fma.rn.f32x2 %0, %1, %2, %0;" : "+l"(accA[i]) : "l"(w2.x), "l"(h2));
            asm("fma.rn.f32x2 %0, %1, %2, %0;" : "+l"(accB[i]) : "l"(w2.y), "l"(h2));
        }
    }
    const int head = q >> 4;
    const int cb = (q & 15) * 4;
    float as0 = att_s[head * Hh + cb],     as1 = att_s[head * Hh + cb + 1],
          as2 = att_s[head * Hh + cb + 2], as3 = att_s[head * Hh + cb + 3];
    float ad0 = att_d[head * Hh + cb],     ad1 = att_d[head * Hh + cb + 1],
          ad2 = att_d[head * Hh + cb + 2], ad3 = att_d[head * Hh + cb + 3];
    #pragma unroll
    for (int i = 0; i < 8; ++i) {
        int n = nb + i;
        float o0, o1, o2, o3;
        asm("mov.b64 {%0, %1}, %2;" : "=f"(o0), "=f"(o1) : "l"(accA[i]));
        asm("mov.b64 {%0, %1}, %2;" : "=f"(o2), "=f"(o3) : "l"(accB[i]));
        float ps = o0 * as0 + o1 * as1 + o2 * as2 + o3 * as3;
        float pd = o0 * ad0 + o1 * ad1 + o2 * ad2 + o3 * ad3;
        #pragma unroll
        for (int off = 8; off > 0; off >>= 1) {
            ps += __shfl_xor_sync(0xffffffffu, ps, off);
            pd += __shfl_xor_sync(0xffffffffu, pd, off);
        }
        if (n < Nn) {
            __half2 ha = __floats2half2_rn(o0, o1);
            __half2 hb = __floats2half2_rn(o2, o3);
            uint2 st;
            st.x = *(unsigned int*)&ha;
            st.y = *(unsigned int*)&hb;
            ((uint2*)d_xph)[(size_t)n * 64 + q] = st;
            if ((q & 15) == 0) {
                d_asrc[n * NHEADS + head] = ps;
                d_adst[n * NHEADS + head] = pd;
            }
        }
    }
}

// ---------------- k_fill: scatter edges into CSR with final attention weight (fp16) ----------------
__global__ void k_fill(const int* __restrict__ src, const int* __restrict__ dst,
                       const float* __restrict__ ea) {
    int e = blockIdx.x * blockDim.x + threadIdx.x;
    if (e >= Ee) return;
    int s = src[e], d = dst[e];
    float4 as = ((const float4*)d_asrc)[s];
    float4 ad = ((const float4*)d_adst)[d];
    float2 e2 = ((const float2*)ea)[e];
    float ex0 = __expf(lrelu(as.x + ad.x + e2.x * d_weff[0] + e2.y * d_weff[1]));
    float ex1 = __expf(lrelu(as.y + ad.y + e2.x * d_weff[2] + e2.y * d_weff[3]));
    float ex2 = __expf(lrelu(as.z + ad.z + e2.x * d_weff[4] + e2.y * d_weff[5]));
    float ex3 = __expf(lrelu(as.w + ad.w + e2.x * d_weff[6] + e2.y * d_weff[7]));
    int pos = atomicAdd(&d_cur[d], 1);
    __half2 e01 = __floats2half2_rn(ex0, ex1);
    __half2 e23 = __floats2half2_rn(ex2, ex3);
    uint4 r;
    r.x = *(unsigned int*)&e01;
    r.y = *(unsigned int*)&e23;
    r.z = (unsigned int)s;
    r.w = 0u;
    d_erec[pos] = r;
}

// ---------------- k_gat: warp-per-node, 4-deep pipelined 512B gathers ----------------
__global__ void __launch_bounds__(256) k_gat(const float* __restrict__ gat_b) {
    __shared__ float sred[8][CC];   // 8KB
    const int t = threadIdx.x;      // 256 = 8 warps
    const int w = t >> 5, lane = t & 31;
    const int head = lane >> 3;
    const int n = blockIdx.x * 8 + w;
    float sacc[8], s2acc[8];
    #pragma unroll
    for (int j = 0; j < 8; ++j) { sacc[j] = 0.f; s2acc[j] = 0.f; }

    if (n < Nn) {
        const float4 b0 = *(const float4*)(gat_b + lane * 8);
        const float4 b1 = *(const float4*)(gat_b + lane * 8 + 4);
        const float we0 = d_weff[head * 2], we1 = d_weff[head * 2 + 1];
        const float ad = d_adst[n * NHEADS + head];
        const float as = d_asrc[n * NHEADS + head];
        const float la0 = d_la[n * 2], la1 = d_la[n * 2 + 1];
        float es = __expf(lrelu(as + ad + la0 * we0 + la1 * we1));
        float den = es;
        float acc[8];
        {
            uint4 xv = *(const uint4*)(d_xph + (size_t)n * CC + lane * 8);
            float2 f0 = __half22float2(*(__half2*)&xv.x);
            float2 f1 = __half22float2(*(__half2*)&xv.y);
            float2 f2 = __half22float2(*(__half2*)&xv.z);
            float2 f3 = __half22float2(*(__half2*)&xv.w);
            acc[0] = es * f0.x; acc[1] = es * f0.y;
            acc[2] = es * f1.x; acc[3] = es * f1.y;
            acc[4] = es * f2.x; acc[5] = es * f2.y;
            acc[6] = es * f3.x; acc[7] = es * f3.y;
        }
        const int p0 = d_ptr[n], p1 = d_cur[n];
        uint4 cc[4];
        #pragma unroll
        for (int j = 0; j < 4; ++j)
            cc[j] = (p0 + j < p1) ? d_erec[p0 + j] : make_uint4(0u, 0u, 0u, 0u);
        for (int i = p0; i < p1; i += 4) {
            float ex[4]; int ss[4];
            #pragma unroll
            for (int j = 0; j < 4; ++j) {
                unsigned int pair = (head < 2) ? cc[j].x : cc[j].y;
                __half2 h2 = *(__half2*)&pair;
                ex[j] = (head & 1) ? __high2float(h2) : __low2float(h2);
                ss[j] = (int)cc[j].z;
            }
            uint4 xv[4];
            #pragma unroll
            for (int j = 0; j < 4; ++j)
                xv[j] = *(const uint4*)(d_xph + (size_t)ss[j] * CC + lane * 8);
            #pragma unroll
            for (int j = 0; j < 4; ++j)
                cc[j] = (i + 4 + j < p1) ? d_erec[i + 4 + j] : make_uint4(0u, 0u, 0u, 0u);
            #pragma unroll
            for (int j = 0; j < 4; ++j) {
                den += ex[j];
                float2 f0 = __half22float2(*(__half2*)&xv[j].x);
                float2 f1 = __half22float2(*(__half2*)&xv[j].y);
                float2 f2 = __half22float2(*(__half2*)&xv[j].z);
                float2 f3 = __half22float2(*(__half2*)&xv[j].w);
                acc[0] = fmaf(ex[j], f0.x, acc[0]); acc[1] = fmaf(ex[j], f0.y, acc[1]);
                acc[2] = fmaf(ex[j], f1.x, acc[2]); acc[3] = fmaf(ex[j], f1.y, acc[3]);
                acc[4] = fmaf(ex[j], f2.x, acc[4]); acc[5] = fmaf(ex[j], f2.y, acc[5]);
                acc[6] = fmaf(ex[j], f3.x, acc[6]); acc[7] = fmaf(ex[j], f3.y, acc[7]);
            }
        }
        float inv = 1.f / den;
        float g0 = acc[0] * inv + b0.x, g1 = acc[1] * inv + b0.y;
        float g2 = acc[2] * inv + b0.z, g3 = acc[3] * inv + b0.w;
        float g4 = acc[4] * inv + b1.x, g5 = acc[5] * inv + b1.y;
        float g6 = acc[6] * inv + b1.z, g7 = acc[7] * inv + b1.w;
        __half2 h01 = __floats2half2_rn(g0, g1);
        __half2 h23 = __floats2half2_rn(g2, g3);
        __half2 h45 = __floats2half2_rn(g4, g5);
        __half2 h67 = __floats2half2_rn(g6, g7);
        uint4 stv;
        stv.x = *(unsigned int*)&h01;
        stv.y = *(unsigned int*)&h23;
        stv.z = *(unsigned int*)&h45;
        stv.w = *(unsigned int*)&h67;
        __stcs((uint4*)(d_gh + (size_t)n * CC + lane * 8), stv);
        sacc[0] = g0; s2acc[0] = g0 * g0;
        sacc[1] = g1; s2acc[1] = g1 * g1;
        sacc[2] = g2; s2acc[2] = g2 * g2;
        sacc[3] = g3; s2acc[3] = g3 * g3;
        sacc[4] = g4; s2acc[4] = g4 * g4;
        sacc[5] = g5; s2acc[5] = g5 * g5;
        sacc[6] = g6; s2acc[6] = g6 * g6;
        sacc[7] = g7; s2acc[7] = g7 * g7;
    }
    #pragma unroll
    for (int j = 0; j < 8; ++j) sred[w][lane * 8 + j] = sacc[j];
    __syncthreads();
    float ts = 0.f;
    #pragma unroll
    for (int ww = 0; ww < 8; ++ww) ts += sred[ww][t];
    __syncthreads();
    #pragma unroll
    for (int j = 0; j < 8; ++j) sred[w][lane * 8 + j] = s2acc[j];
    __syncthreads();
    float ts2 = 0.f;
    #pragma unroll
    for (int ww = 0; ww < 8; ++ww) ts2 += sred[ww][t];
    atomicAdd(&d_sum2[t], ts);
    atomicAdd(&d_sum2[CC + t], ts2);
}

// ---------------- k_out: inline stats2 + 8 nodes per block ----------------
__global__ void k_out(const float* __restrict__ n2b,
                      const float* __restrict__ n2w,
                      const float* __restrict__ n2ms,
                      const float* __restrict__ ow,
                      const float* __restrict__ ob,
                      float* __restrict__ out) {
    __shared__ float red[8][8][4];   // [warp][node][out]
    const int nb = blockIdx.x * 8;
    const int t = threadIdx.x;  // 256
    const int w = t >> 5;
    const float w0 = ow[t], w1 = ow[CC + t], w2 = ow[2 * CC + t], w3 = ow[3 * CC + t];
    // inline stats2 (d_sum2 finalized by k_gat)
    float m  = d_sum2[t]      * (1.f / Nn);
    float m2 = d_sum2[CC + t] * (1.f / Nn);
    float msv = n2ms[t];
    float var = m2 - (2.f * msv - msv * msv) * m * m;
    const float mu = msv * m;
    const float sc = n2w[t] * rsqrtf(var + EPSN);
    const float bb = n2b[t];
    #pragma unroll
    for (int i = 0; i < 8; ++i) {
        int n = nb + i;
        float y = 0.f;
        if (n < Nn) {
            float gv = __half2float(__ldcs(d_gh + (size_t)n * CC + t));
            y = eluf(sc * (gv - mu) + bb);
        }
        float p0 = y * w0, p1 = y * w1, p2 = y * w2, p3 = y * w3;
        #pragma unroll
        for (int off = 16; off > 0; off >>= 1) {
            p0 += __shfl_xor_sync(0xffffffffu, p0, off);
            p1 += __shfl_xor_sync(0xffffffffu, p1, off);
            p2 += __shfl_xor_sync(0xffffffffu, p2, off);
            p3 += __shfl_xor_sync(0xffffffffu, p3, off);
        }
        if ((t & 31) == 0) {
            red[w][i][0] = p0; red[w][i][1] = p1;
            red[w][i][2] = p2; red[w][i][3] = p3;
        }
    }
    __syncthreads();
    if (t < 32) {
        int i = t >> 2, o = t & 3;
        int n = nb + i;
        if (n < Nn) {
            float s = ob[o];
            #pragma unroll
            for (int ww = 0; ww < 8; ++ww) s += red[ww][i][o];
            out[n * 4 + o] = fmaxf(s, 0.f);
        }
    }
}

// ---------------- host ----------------
extern "C" void kernel_launch(void* const* d_in, const int* in_sizes, int n_in,
                              void* d_out, int out_size) {
    const float* x     = (const float*)d_in[0];
    const float* ea    = (const float*)d_in[1];
    const float* swl   = (const float*)d_in[2];
    const float* sbl   = (const float*)d_in[3];
    const float* swr   = (const float*)d_in[4];
    const float* n1w   = (const float*)d_in[5];
    const float* n1b   = (const float*)d_in[6];
    const float* n1ms  = (const float*)d_in[7];
    const float* gatw  = (const float*)d_in[8];
    const float* atts  = (const float*)d_in[9];
    const float* attd  = (const float*)d_in[10];
    const float* atte  = (const float*)d_in[11];
    const float* gatwe = (const float*)d_in[12];
    const float* gatb  = (const float*)d_in[13];
    const float* n2w   = (const float*)d_in[14];
    const float* n2b   = (const float*)d_in[15];
    const float* n2ms  = (const float*)d_in[16];
    const float* outw  = (const float*)d_in[17];
    const float* outb  = (const float*)d_in[18];
    const int*   eidx  = (const int*)d_in[19];
    const int* src = eidx;
    const int* dst = eidx + Ee;
    float* out = (float*)d_out;

    void* p_nacc;
    cudaGetSymbolAddress(&p_nacc, d_nacc);
    cudaMemsetAsync(p_nacc, 0, sizeof(float) * Nn * 8);

    k_prep<<<1, 256>>>(gatw, atte, gatwe);
    k_eagg<<<(Ee + 255) / 256, 256>>>(src, dst, x, ea);
    k_node1<<<(Nn + 3) / 4, 256>>>(x, swl, sbl, swr);
    k_scan1<<<NSB, 1024>>>();
    k_scan2<<<1, 128>>>();
    k_xp<<<(Nn + 7) / 8, 64>>>(n1b, n1w, n1ms, atts, attd);
    k_fill<<<(Ee + 255) / 256, 256>>>(src, dst, ea);
    k_gat<<<(Nn + 7) / 8, 256>>>(gatb);
    k_out<<<(Nn + 7) / 8, 256>>>(n2b, n2w, n2ms, outw, outb, out);
}